// round 13
// baseline (speedup 1.0000x reference)
#include <cuda_runtime.h>
#include <cuda_fp16.h>
#include <cstdint>

#define SEQ 2048
#define DIM 2048
#define NH  16
#define HD  128
#define TD  (3*DIM)
#define LN_EPS 1e-5f

// ---------------- scratch (static device globals; no allocation) ----------------
__device__ __half g_xn_h[(size_t)SEQ*DIM];    // f16 LN output (GEMM A operand + residual)
__device__ __half g_qkv_h[(size_t)SEQ*TD];    // f16 QKV
__device__ __half g_attn_h[(size_t)SEQ*DIM];  // f16 attention output
__device__ __half g_w1_h[(size_t)TD*DIM];
__device__ __half g_w2_h[(size_t)DIM*DIM];

__device__ __forceinline__ float4 ld4(const float* p){ return *(const float4*)p; }

// ---------------- MMA helpers ----------------
__device__ __forceinline__ uint32_t smem_u32(const void* p){
    uint32_t a; asm("{ .reg .u64 t; cvta.to.shared.u64 t, %1; cvt.u32.u64 %0, t; }" : "=r"(a) : "l"(p)); return a;
}
__device__ __forceinline__ void ldsm4(uint32_t& r0, uint32_t& r1, uint32_t& r2, uint32_t& r3, uint32_t a){
    asm volatile("ldmatrix.sync.aligned.m8n8.x4.shared.b16 {%0,%1,%2,%3}, [%4];"
                 : "=r"(r0), "=r"(r1), "=r"(r2), "=r"(r3) : "r"(a));
}
__device__ __forceinline__ void ldsm4t(uint32_t& r0, uint32_t& r1, uint32_t& r2, uint32_t& r3, uint32_t a){
    asm volatile("ldmatrix.sync.aligned.m8n8.x4.trans.shared.b16 {%0,%1,%2,%3}, [%4];"
                 : "=r"(r0), "=r"(r1), "=r"(r2), "=r"(r3) : "r"(a));
}
__device__ __forceinline__ void mma16816(float* c, uint32_t a0, uint32_t a1, uint32_t a2, uint32_t a3,
                                         uint32_t b0, uint32_t b1){
    asm volatile("mma.sync.aligned.m16n8k16.row.col.f32.f16.f16.f32 "
                 "{%0,%1,%2,%3}, {%4,%5,%6,%7}, {%8,%9}, {%0,%1,%2,%3};"
                 : "+f"(c[0]), "+f"(c[1]), "+f"(c[2]), "+f"(c[3])
                 : "r"(a0), "r"(a1), "r"(a2), "r"(a3), "r"(b0), "r"(b1));
}
__device__ __forceinline__ void cpasync16(uint32_t dst, const void* src){
    asm volatile("cp.async.cg.shared.global [%0], [%1], 16;" :: "r"(dst), "l"(src));
}
__device__ __forceinline__ uint32_t h2u(__half2 h){ return *(uint32_t*)&h; }

// ================= HMMA f16 GEMM-NT: 128x128 tile, BK=64, 3-stage swizzled, 1 sync/iter =================
#define BK 64
#define STG_A (128 * 128)                // 16384 B per tile
#define STG_BYTES (2 * STG_A)            // 32768
#define GEMM_SMEM (3 * STG_BYTES)        // 98304 -> 2 CTA/SM

__global__ void __launch_bounds__(256) h_gemm(
    const __half* __restrict__ A, const __half* __restrict__ B,
    const float* __restrict__ bias, const __half* __restrict__ resid,
    float* __restrict__ Cf, __half* __restrict__ Ch, int M, int N, int K)
{
    extern __shared__ char smc[];
    uint32_t base = smem_u32(smc);

    int t = threadIdx.x, lane = t & 31, w = t >> 5;
    int bm = blockIdx.y * 128, bn = blockIdx.x * 128;
    int wm = (w >> 2) * 64, wn = (w & 3) * 32;

    int a_row = wm + (lane & 7) + ((lane & 8) ? 8 : 0);
    int a_kc  = (lane & 16) ? 1 : 0;
    int b_row = wn + (lane & 7) + ((lane & 16) ? 8 : 0);
    int b_kc  = (lane & 8) ? 1 : 0;

    float acc[4][4][4];
    #pragma unroll
    for (int i = 0; i < 4; i++)
        #pragma unroll
        for (int j = 0; j < 4; j++)
            #pragma unroll
            for (int c = 0; c < 4; c++) acc[i][j][c] = 0.f;

    int niter = K / BK;

    auto load_stage = [&](int stg, int kc){
        uint32_t ab = base + stg * STG_BYTES;
        uint32_t bb = ab + STG_A;
        const __half* Ak = A + (size_t)kc * BK;
        const __half* Bk = B + (size_t)kc * BK;
        #pragma unroll
        for (int i = 0; i < 4; i++) {
            int vid = t + i * 256;
            int row = vid >> 3, c = vid & 7;
            int sw = ((c ^ (row & 7)) << 4);
            cpasync16(ab + row * 128 + sw, Ak + (size_t)(bm + row) * K + c * 8);
        }
        #pragma unroll
        for (int i = 0; i < 4; i++) {
            int vid = t + i * 256;
            int row = vid >> 3, c = vid & 7;
            int sw = ((c ^ (row & 7)) << 4);
            cpasync16(bb + row * 128 + sw, Bk + (size_t)(bn + row) * K + c * 8);
        }
        asm volatile("cp.async.commit_group;" ::: "memory");
    };

    load_stage(0, 0);
    if (niter > 1) load_stage(1, 1);

    for (int kt = 0; kt < niter; kt++) {
        if (kt + 1 < niter) {
            asm volatile("cp.async.wait_group 1;" ::: "memory");
        } else {
            asm volatile("cp.async.wait_group 0;" ::: "memory");
        }
        __syncthreads();
        if (kt + 2 < niter) load_stage((kt + 2) % 3, kt + 2);

        int stg = kt % 3;
        uint32_t abase = base + stg * STG_BYTES;
        uint32_t bbase = abase + STG_A;
        #pragma unroll
        for (int ks = 0; ks < 4; ks++) {
            uint32_t a[4][4], b[2][4];
            #pragma unroll
            for (int i = 0; i < 4; i++) {
                int ar = a_row + i * 16;
                int ch = ks * 2 + a_kc;
                uint32_t addr = abase + ar * 128 + (((ch ^ (ar & 7)) << 4));
                ldsm4(a[i][0], a[i][1], a[i][2], a[i][3], addr);
            }
            #pragma unroll
            for (int p = 0; p < 2; p++) {
                int br = b_row + p * 16;
                int ch = ks * 2 + b_kc;
                uint32_t addr = bbase + br * 128 + (((ch ^ (br & 7)) << 4));
                ldsm4(b[p][0], b[p][1], b[p][2], b[p][3], addr);
            }
            #pragma unroll
            for (int i = 0; i < 4; i++) {
                #pragma unroll
                for (int j = 0; j < 4; j++) {
                    int p = j >> 1;
                    uint32_t bb0 = (j & 1) ? b[p][2] : b[p][0];
                    uint32_t bb1 = (j & 1) ? b[p][3] : b[p][1];
                    mma16816(acc[i][j], a[i][0], a[i][1], a[i][2], a[i][3], bb0, bb1);
                }
            }
        }
    }

    int mrow = bm + wm + (lane >> 2);
    int ncol = bn + wn + 2 * (lane & 3);
    #pragma unroll
    for (int i = 0; i < 4; i++) {
        #pragma unroll
        for (int j = 0; j < 4; j++) {
            int n0 = ncol + j * 8;
            float b0 = bias[n0], b1 = bias[n0 + 1];
            int m0 = mrow + i * 16;
            size_t rb0 = (size_t)m0 * N + n0;
            size_t rb1 = (size_t)(m0 + 8) * N + n0;
            float2 v0 = { acc[i][j][0] + b0, acc[i][j][1] + b1 };
            float2 v1 = { acc[i][j][2] + b0, acc[i][j][3] + b1 };
            if (Ch) {
                *(uint32_t*)(Ch + rb0) = h2u(__floats2half2_rn(v0.x, v0.y));
                *(uint32_t*)(Ch + rb1) = h2u(__floats2half2_rn(v1.x, v1.y));
            } else {
                if (resid) {
                    float2 r0 = __half22float2(*(const __half2*)(resid + rb0));
                    float2 r1 = __half22float2(*(const __half2*)(resid + rb1));
                    v0.x += r0.x; v0.y += r0.y; v1.x += r1.x; v1.y += r1.y;
                }
                *(float2*)(Cf + rb0) = v0;
                *(float2*)(Cf + rb1) = v1;
            }
        }
    }
}

// ======================= HMMA flash attention: 256 threads, BQ=128, 3-stage KV ring =======================
#define TSTR2 136
#define TILE_E (64 * TSTR2)
#define STAGE_E (2 * TILE_E)
#define NSTAGE 3
#define ATTN_SMEM (NSTAGE * STAGE_E * 2 + NSTAGE * 256 + 256)

__global__ void __launch_bounds__(256, 1) k_attn_h(
    const int* __restrict__ seg,
    const __half* __restrict__ qkv,
    __half* __restrict__ attn_out)
{
    extern __shared__ char smc[];
    __half* buf = (__half*)smc;
    uint32_t buf_u = smem_u32(buf);
    uint32_t sks_u = buf_u + NSTAGE * STAGE_E * 2;
    int* sks = (int*)(smc + NSTAGE * STAGE_E * 2);

    const int t = threadIdx.x, lane = t & 31, w = t >> 5;
    const int q0 = blockIdx.x * 128, h = blockIdx.y;
    const int wq = w * 16;
    const float scale = 0.08838834764831845f;

    const int ldrow = (lane & 7) + ((lane & 8) ? 8 : 0);
    const int a_kof = (lane & 16) ? 8 : 0;
    const int b_row = (lane & 7) + ((lane & 16) ? 8 : 0);
    const int b_kof = (lane & 8) ? 8 : 0;
    const int v_col = (lane & 16) ? 8 : 0;

    // ---- load Q tile [128 x 128] into smem (stage-0 area), then to regs ----
    #pragma unroll
    for (int i = 0; i < 8; i++) {
        int vid = t + i * 256;
        int row = vid >> 4, c = vid & 15;
        cpasync16(buf_u + (row * TSTR2 + c * 8) * 2,
                  qkv + (size_t)(q0 + row) * TD + h * HD + c * 8);
    }
    asm volatile("cp.async.commit_group;" ::: "memory");
    asm volatile("cp.async.wait_group 0;" ::: "memory");
    __syncthreads();

    uint32_t qa[8][4];
    #pragma unroll
    for (int ks = 0; ks < 8; ks++) {
        uint32_t addr = buf_u + (((wq + ldrow) * TSTR2) + ks * 16 + a_kof) * 2;
        ldsm4(qa[ks][0], qa[ks][1], qa[ks][2], qa[ks][3], addr);
    }
    int sq0 = seg[q0 + wq + (lane >> 2)];
    int sq1 = seg[q0 + wq + (lane >> 2) + 8];
    __syncthreads();

    float mv[2] = { -1e30f, -1e30f }, lv[2] = { 0.f, 0.f };
    float o[16][4];
    #pragma unroll
    for (int j = 0; j < 16; j++)
        #pragma unroll
        for (int c = 0; c < 4; c++) o[j][c] = 0.f;

    // KV stage loader (one commit group per stage)
    auto load_kv = [&](int stg, int kt){
        int kb = kt * 64;
        uint32_t sb = buf_u + stg * STAGE_E * 2;
        #pragma unroll
        for (int i = 0; i < 4; i++) {
            int vid = t + i * 256;
            int row = vid >> 4, c = vid & 15;
            cpasync16(sb + (row * TSTR2 + c * 8) * 2,
                      qkv + (size_t)(kb + row) * TD + DIM + h * HD + c * 8);
            cpasync16(sb + (TILE_E + row * TSTR2 + c * 8) * 2,
                      qkv + (size_t)(kb + row) * TD + 2 * DIM + h * HD + c * 8);
        }
        if (t < 16) cpasync16(sks_u + stg * 256 + t * 16, seg + kb + t * 4);
        asm volatile("cp.async.commit_group;" ::: "memory");
    };

    const int NT = SEQ / 64;
    load_kv(0, 0);
    load_kv(1, 1);

    for (int kt = 0; kt < NT; kt++) {
        if (kt + 1 < NT) {
            asm volatile("cp.async.wait_group 1;" ::: "memory");
        } else {
            asm volatile("cp.async.wait_group 0;" ::: "memory");
        }
        __syncthreads();
        if (kt + 2 < NT) load_kv((kt + 2) % NSTAGE, kt + 2);

        int st = kt % NSTAGE;
        uint32_t kbase = buf_u + st * STAGE_E * 2;
        uint32_t vbase = kbase + TILE_E * 2;
        const int* skp = sks + st * 64;

        float s[8][4];
        #pragma unroll
        for (int j = 0; j < 8; j++)
            #pragma unroll
            for (int c = 0; c < 4; c++) s[j][c] = 0.f;

        #pragma unroll
        for (int ks = 0; ks < 8; ks++) {
            uint32_t kb_[4][4];
            #pragma unroll
            for (int g = 0; g < 4; g++) {
                uint32_t addr = kbase + (((g * 16 + b_row) * TSTR2) + ks * 16 + b_kof) * 2;
                ldsm4(kb_[g][0], kb_[g][1], kb_[g][2], kb_[g][3], addr);
            }
            #pragma unroll
            for (int g = 0; g < 4; g++) {
                mma16816(s[2*g],   qa[ks][0], qa[ks][1], qa[ks][2], qa[ks][3], kb_[g][0], kb_[g][1]);
                mma16816(s[2*g+1], qa[ks][0], qa[ks][1], qa[ks][2], qa[ks][3], kb_[g][2], kb_[g][3]);
            }
        }

        #pragma unroll
        for (int rh = 0; rh < 2; rh++) {
            int sqv = rh ? sq1 : sq0;
            float rm = -1e30f;
            #pragma unroll
            for (int j = 0; j < 8; j++) {
                #pragma unroll
                for (int cc = 0; cc < 2; cc++) {
                    int col = 8 * j + 2 * (lane & 3) + cc;
                    float v = s[j][2*rh+cc] * scale + ((sqv == skp[col]) ? 1.0f : 0.0f);
                    s[j][2*rh+cc] = v;
                    rm = fmaxf(rm, v);
                }
            }
            rm = fmaxf(rm, __shfl_xor_sync(0xffffffffu, rm, 1));
            rm = fmaxf(rm, __shfl_xor_sync(0xffffffffu, rm, 2));
            float mnew = fmaxf(mv[rh], rm);
            float corr = __expf(mv[rh] - mnew);
            mv[rh] = mnew;
            float rs = 0.f;
            #pragma unroll
            for (int j = 0; j < 8; j++) {
                #pragma unroll
                for (int cc = 0; cc < 2; cc++) {
                    float e = __expf(s[j][2*rh+cc] - mnew);
                    s[j][2*rh+cc] = e;
                    rs += e;
                }
            }
            rs += __shfl_xor_sync(0xffffffffu, rs, 1);
            rs += __shfl_xor_sync(0xffffffffu, rs, 2);
            lv[rh] = lv[rh] * corr + rs;
            #pragma unroll
            for (int j = 0; j < 16; j++) {
                o[j][2*rh]   *= corr;
                o[j][2*rh+1] *= corr;
            }
        }

        uint32_t pa[4][4];
        #pragma unroll
        for (int kk = 0; kk < 4; kk++) {
            pa[kk][0] = h2u(__floats2half2_rn(s[2*kk][0],   s[2*kk][1]));
            pa[kk][1] = h2u(__floats2half2_rn(s[2*kk][2],   s[2*kk][3]));
            pa[kk][2] = h2u(__floats2half2_rn(s[2*kk+1][0], s[2*kk+1][1]));
            pa[kk][3] = h2u(__floats2half2_rn(s[2*kk+1][2], s[2*kk+1][3]));
        }

        #pragma unroll
        for (int kk = 0; kk < 4; kk++) {
            #pragma unroll
            for (int g = 0; g < 8; g++) {
                uint32_t vb0, vb1, vb2, vb3;
                uint32_t addr = vbase + (((kk * 16 + ldrow) * TSTR2) + g * 16 + v_col) * 2;
                ldsm4t(vb0, vb1, vb2, vb3, addr);
                mma16816(o[2*g],   pa[kk][0], pa[kk][1], pa[kk][2], pa[kk][3], vb0, vb1);
                mma16816(o[2*g+1], pa[kk][0], pa[kk][1], pa[kk][2], pa[kk][3], vb2, vb3);
            }
        }
    }

    float inv0 = 1.0f / lv[0], inv1 = 1.0f / lv[1];
    int r0 = q0 + wq + (lane >> 2);
    int colb = 2 * (lane & 3);
    #pragma unroll
    for (int j = 0; j < 16; j++) {
        int col = h * HD + 8 * j + colb;
        *(uint32_t*)(attn_out + (size_t)r0 * DIM + col) =
            h2u(__floats2half2_rn(o[j][0] * inv0, o[j][1] * inv0));
        *(uint32_t*)(attn_out + (size_t)(r0 + 8) * DIM + col) =
            h2u(__floats2half2_rn(o[j][2] * inv1, o[j][3] * inv1));
    }
}

// ======================= fused prep: weight converts + embed+LN in ONE launch =======================
#define NB_W1 (TD * DIM / 8 / 256)    // 6144
#define NB_W2 (DIM * DIM / 8 / 256)   // 2048

__global__ void __launch_bounds__(256) k_prep(
    const float* __restrict__ in_w,
    const float* __restrict__ out_w,
    const float* __restrict__ byte_repr,
    const int*   __restrict__ cats,
    const int*   __restrict__ cse,
    const int*   __restrict__ comb,
    const float* __restrict__ cat_emb,
    const float* __restrict__ case_emb,
    const float* __restrict__ comb_emb,
    const float* __restrict__ g,
    const float* __restrict__ b)
{
    int blk = blockIdx.x;
    int t = threadIdx.x;

    if (blk < NB_W1 + NB_W2) {
        const float* src = (blk < NB_W1) ? in_w : out_w;
        __half* dst = (blk < NB_W1) ? g_w1_h : g_w2_h;
        int i = (blk < NB_W1 ? blk : blk - NB_W1) * 256 + t;
        float4 a = ld4(src + (size_t)i * 8);
        float4 c = ld4(src + (size_t)i * 8 + 4);
        __half2 h[4];
        h[0] = __floats2half2_rn(a.x, a.y);
        h[1] = __floats2half2_rn(a.z, a.w);
        h[2] = __floats2half2_rn(c.x, c.y);
        h[3] = __floats2half2_rn(c.z, c.w);
        *(uint4*)(dst + (size_t)i * 8) = *(uint4*)h;
        return;
    }

    int s = blk - (NB_W1 + NB_W2);
    int lane = t & 31, wid = t >> 5;
    int c0 = t * 4;
    int c1 = 1024 + t * 4;

    size_t catb = (size_t)cats[s] * DIM;
    size_t cab  = (size_t)cse[s]  * DIM;
    size_t cob  = (size_t)comb[s] * DIM;
    const float* base = byte_repr + (size_t)s * DIM;

    float x[8];
    {
        float4 a = ld4(base + c0), e = ld4(cat_emb + catb + c0);
        float4 f = ld4(case_emb + cab + c0), h = ld4(comb_emb + cob + c0);
        x[0] = a.x + e.x + f.x + h.x;  x[1] = a.y + e.y + f.y + h.y;
        x[2] = a.z + e.z + f.z + h.z;  x[3] = a.w + e.w + f.w + h.w;
    }
    {
        float4 a = ld4(base + c1), e = ld4(cat_emb + catb + c1);
        float4 f = ld4(case_emb + cab + c1), h = ld4(comb_emb + cob + c1);
        x[4] = a.x + e.x + f.x + h.x;  x[5] = a.y + e.y + f.y + h.y;
        x[6] = a.z + e.z + f.z + h.z;  x[7] = a.w + e.w + f.w + h.w;
    }

    __shared__ float red[8];
    __shared__ float s_bcast;

    float sum = 0.f;
    #pragma unroll
    for (int i = 0; i < 8; i++) sum += x[i];
    #pragma unroll
    for (int o = 16; o > 0; o >>= 1) sum += __shfl_xor_sync(0xffffffffu, sum, o);
    if (lane == 0) red[wid] = sum;
    __syncthreads();
    if (t == 0) {
        float v = 0.f;
        #pragma unroll
        for (int i = 0; i < 8; i++) v += red[i];
        s_bcast = v * (1.0f / DIM);
    }
    __syncthreads();
    float mu = s_bcast;
    __syncthreads();

    float sq = 0.f;
    #pragma unroll
    for (int i = 0; i < 8; i++) { float d = x[i] - mu; sq += d * d; }
    #pragma unroll
    for (int o = 16; o > 0; o >>= 1) sq += __shfl_xor_sync(0xffffffffu, sq, o);
    if (lane == 0) red[wid] = sq;
    __syncthreads();
    if (t == 0) {
        float v = 0.f;
        #pragma unroll
        for (int i = 0; i < 8; i++) v += red[i];
        s_bcast = rsqrtf(v * (1.0f / DIM) + LN_EPS);
    }
    __syncthreads();
    float rs = s_bcast;

    __half* dsth = g_xn_h + (size_t)s * DIM;
    {
        float4 gg = ld4(g + c0), bb = ld4(b + c0);
        float4 o;
        o.x = (x[0] - mu) * rs * gg.x + bb.x;
        o.y = (x[1] - mu) * rs * gg.y + bb.y;
        o.z = (x[2] - mu) * rs * gg.z + bb.z;
        o.w = (x[3] - mu) * rs * gg.w + bb.w;
        __half2 h2[2] = { __floats2half2_rn(o.x, o.y), __floats2half2_rn(o.z, o.w) };
        *(uint2*)(dsth + c0) = *(uint2*)h2;
    }
    {
        float4 gg = ld4(g + c1), bb = ld4(b + c1);
        float4 o;
        o.x = (x[4] - mu) * rs * gg.x + bb.x;
        o.y = (x[5] - mu) * rs * gg.y + bb.y;
        o.z = (x[6] - mu) * rs * gg.z + bb.z;
        o.w = (x[7] - mu) * rs * gg.w + bb.w;
        __half2 h2[2] = { __floats2half2_rn(o.x, o.y), __floats2half2_rn(o.z, o.w) };
        *(uint2*)(dsth + c1) = *(uint2*)h2;
    }
}

// ======================= launcher =======================
extern "C" void kernel_launch(void* const* d_in, const int* in_sizes, int n_in,
                              void* d_out, int out_size)
{
    const float* byte_repr = (const float*)d_in[0];
    const int*   categories= (const int*)  d_in[1];
    const int*   cse       = (const int*)  d_in[2];
    const int*   comb      = (const int*)  d_in[3];
    const int*   seg_ids   = (const int*)  d_in[4];
    const float* cat_emb   = (const float*)d_in[5];
    const float* case_emb  = (const float*)d_in[6];
    const float* comb_emb  = (const float*)d_in[7];
    const float* ln_g      = (const float*)d_in[8];
    const float* ln_b      = (const float*)d_in[9];
    const float* in_w      = (const float*)d_in[10];
    const float* in_b      = (const float*)d_in[11];
    const float* out_w     = (const float*)d_in[12];
    const float* out_b     = (const float*)d_in[13];
    float* out = (float*)d_out;

    __half *p_xn_h, *p_qkv_h, *p_attn_h, *p_w1_h, *p_w2_h;
    cudaGetSymbolAddress((void**)&p_xn_h,  g_xn_h);
    cudaGetSymbolAddress((void**)&p_qkv_h, g_qkv_h);
    cudaGetSymbolAddress((void**)&p_attn_h,g_attn_h);
    cudaGetSymbolAddress((void**)&p_w1_h,  g_w1_h);
    cudaGetSymbolAddress((void**)&p_w2_h,  g_w2_h);

    cudaFuncSetAttribute(k_attn_h, cudaFuncAttributeMaxDynamicSharedMemorySize, ATTN_SMEM);
    cudaFuncSetAttribute(h_gemm, cudaFuncAttributeMaxDynamicSharedMemorySize, GEMM_SMEM);

    // 1) fused prep: both weight converts + embed+LN in one launch
    k_prep<<<NB_W1 + NB_W2 + SEQ, 256>>>(in_w, out_w, byte_repr, categories, cse, comb,
                                         cat_emb, case_emb, comb_emb, ln_g, ln_b);

    // 2) QKV projection -> f16
    dim3 gq(TD / 128, SEQ / 128);
    h_gemm<<<gq, 256, GEMM_SMEM>>>(p_xn_h, p_w1_h, in_b, nullptr, nullptr, p_qkv_h, SEQ, TD, DIM);

    // 3) HMMA flash attention (256 threads, BQ=128, 3-stage KV ring)
    dim3 ga(SEQ / 128, NH);
    k_attn_h<<<ga, 256, ATTN_SMEM>>>(seg_ids, p_qkv_h, p_attn_h);

    // 4) out projection + f16 residual -> fp32 out
    dim3 go(DIM / 128, SEQ / 128);
    h_gemm<<<go, 256, GEMM_SMEM>>>(p_attn_h, p_w2_h, out_b, p_xn_h, out, nullptr, SEQ, DIM, DIM);
}

// round 14
// speedup vs baseline: 1.0176x; 1.0176x over previous
#include <cuda_runtime.h>
#include <cuda_fp16.h>
#include <cstdint>

#define SEQ 2048
#define DIM 2048
#define NH  16
#define HD  128
#define TD  (3*DIM)
#define LN_EPS 1e-5f

// ---------------- scratch (static device globals; no allocation) ----------------
__device__ __half g_xn_h[(size_t)SEQ*DIM];    // f16 LN output (GEMM A operand + residual)
__device__ __half g_qkv_h[(size_t)SEQ*TD];    // f16 QKV
__device__ __half g_attn_h[(size_t)SEQ*DIM];  // f16 attention output
__device__ __half g_w1_h[(size_t)TD*DIM];
__device__ __half g_w2_h[(size_t)DIM*DIM];

__device__ __forceinline__ float4 ld4(const float* p){ return *(const float4*)p; }

// ---------------- MMA helpers ----------------
__device__ __forceinline__ uint32_t smem_u32(const void* p){
    uint32_t a; asm("{ .reg .u64 t; cvta.to.shared.u64 t, %1; cvt.u32.u64 %0, t; }" : "=r"(a) : "l"(p)); return a;
}
__device__ __forceinline__ void ldsm4(uint32_t& r0, uint32_t& r1, uint32_t& r2, uint32_t& r3, uint32_t a){
    asm volatile("ldmatrix.sync.aligned.m8n8.x4.shared.b16 {%0,%1,%2,%3}, [%4];"
                 : "=r"(r0), "=r"(r1), "=r"(r2), "=r"(r3) : "r"(a));
}
__device__ __forceinline__ void ldsm4t(uint32_t& r0, uint32_t& r1, uint32_t& r2, uint32_t& r3, uint32_t a){
    asm volatile("ldmatrix.sync.aligned.m8n8.x4.trans.shared.b16 {%0,%1,%2,%3}, [%4];"
                 : "=r"(r0), "=r"(r1), "=r"(r2), "=r"(r3) : "r"(a));
}
__device__ __forceinline__ void mma16816(float* c, uint32_t a0, uint32_t a1, uint32_t a2, uint32_t a3,
                                         uint32_t b0, uint32_t b1){
    asm volatile("mma.sync.aligned.m16n8k16.row.col.f32.f16.f16.f32 "
                 "{%0,%1,%2,%3}, {%4,%5,%6,%7}, {%8,%9}, {%0,%1,%2,%3};"
                 : "+f"(c[0]), "+f"(c[1]), "+f"(c[2]), "+f"(c[3])
                 : "r"(a0), "r"(a1), "r"(a2), "r"(a3), "r"(b0), "r"(b1));
}
__device__ __forceinline__ void cpasync16(uint32_t dst, const void* src){
    asm volatile("cp.async.cg.shared.global [%0], [%1], 16;" :: "r"(dst), "l"(src));
}
__device__ __forceinline__ uint32_t h2u(__half2 h){ return *(uint32_t*)&h; }

// ================= HMMA f16 GEMM-NT: 128x128 tile, BK=64, 3-stage swizzled, 1 sync/iter =================
// Optional piggyback convert: blocks with blockIdx.y == gridDim.y-1 (when csrc != null)
// perform a grid-stride fp32->f16 convert instead of GEMM work.
#define BK 64
#define STG_A (128 * 128)                // 16384 B per tile
#define STG_BYTES (2 * STG_A)            // 32768
#define GEMM_SMEM (3 * STG_BYTES)        // 98304 -> 2 CTA/SM

__global__ void __launch_bounds__(256) h_gemm(
    const __half* __restrict__ A, const __half* __restrict__ B,
    const float* __restrict__ bias, const __half* __restrict__ resid,
    float* __restrict__ Cf, __half* __restrict__ Ch, int M, int N, int K,
    const float* __restrict__ csrc, __half* __restrict__ cdst, int cn8)
{
    extern __shared__ char smc[];
    uint32_t base = smem_u32(smc);

    int t = threadIdx.x, lane = t & 31, w = t >> 5;

    // ---- piggyback convert row ----
    if (csrc && (int)blockIdx.y == (int)gridDim.y - 1) {
        int stride = gridDim.x * 256;
        for (int i = blockIdx.x * 256 + t; i < cn8; i += stride) {
            float4 a = ld4(csrc + (size_t)i * 8);
            float4 c = ld4(csrc + (size_t)i * 8 + 4);
            __half2 h[4];
            h[0] = __floats2half2_rn(a.x, a.y);
            h[1] = __floats2half2_rn(a.z, a.w);
            h[2] = __floats2half2_rn(c.x, c.y);
            h[3] = __floats2half2_rn(c.z, c.w);
            *(uint4*)(cdst + (size_t)i * 8) = *(uint4*)h;
        }
        return;
    }

    int bm = blockIdx.y * 128, bn = blockIdx.x * 128;
    int wm = (w >> 2) * 64, wn = (w & 3) * 32;

    int a_row = wm + (lane & 7) + ((lane & 8) ? 8 : 0);
    int a_kc  = (lane & 16) ? 1 : 0;
    int b_row = wn + (lane & 7) + ((lane & 16) ? 8 : 0);
    int b_kc  = (lane & 8) ? 1 : 0;

    float acc[4][4][4];
    #pragma unroll
    for (int i = 0; i < 4; i++)
        #pragma unroll
        for (int j = 0; j < 4; j++)
            #pragma unroll
            for (int c = 0; c < 4; c++) acc[i][j][c] = 0.f;

    int niter = K / BK;

    auto load_stage = [&](int stg, int kc){
        uint32_t ab = base + stg * STG_BYTES;
        uint32_t bb = ab + STG_A;
        const __half* Ak = A + (size_t)kc * BK;
        const __half* Bk = B + (size_t)kc * BK;
        #pragma unroll
        for (int i = 0; i < 4; i++) {
            int vid = t + i * 256;
            int row = vid >> 3, c = vid & 7;
            int sw = ((c ^ (row & 7)) << 4);
            cpasync16(ab + row * 128 + sw, Ak + (size_t)(bm + row) * K + c * 8);
        }
        #pragma unroll
        for (int i = 0; i < 4; i++) {
            int vid = t + i * 256;
            int row = vid >> 3, c = vid & 7;
            int sw = ((c ^ (row & 7)) << 4);
            cpasync16(bb + row * 128 + sw, Bk + (size_t)(bn + row) * K + c * 8);
        }
        asm volatile("cp.async.commit_group;" ::: "memory");
    };

    load_stage(0, 0);
    if (niter > 1) load_stage(1, 1);

    for (int kt = 0; kt < niter; kt++) {
        if (kt + 1 < niter) {
            asm volatile("cp.async.wait_group 1;" ::: "memory");
        } else {
            asm volatile("cp.async.wait_group 0;" ::: "memory");
        }
        __syncthreads();
        if (kt + 2 < niter) load_stage((kt + 2) % 3, kt + 2);

        int stg = kt % 3;
        uint32_t abase = base + stg * STG_BYTES;
        uint32_t bbase = abase + STG_A;
        #pragma unroll
        for (int ks = 0; ks < 4; ks++) {
            uint32_t a[4][4], b[2][4];
            #pragma unroll
            for (int i = 0; i < 4; i++) {
                int ar = a_row + i * 16;
                int ch = ks * 2 + a_kc;
                uint32_t addr = abase + ar * 128 + (((ch ^ (ar & 7)) << 4));
                ldsm4(a[i][0], a[i][1], a[i][2], a[i][3], addr);
            }
            #pragma unroll
            for (int p = 0; p < 2; p++) {
                int br = b_row + p * 16;
                int ch = ks * 2 + b_kc;
                uint32_t addr = bbase + br * 128 + (((ch ^ (br & 7)) << 4));
                ldsm4(b[p][0], b[p][1], b[p][2], b[p][3], addr);
            }
            #pragma unroll
            for (int i = 0; i < 4; i++) {
                #pragma unroll
                for (int j = 0; j < 4; j++) {
                    int p = j >> 1;
                    uint32_t bb0 = (j & 1) ? b[p][2] : b[p][0];
                    uint32_t bb1 = (j & 1) ? b[p][3] : b[p][1];
                    mma16816(acc[i][j], a[i][0], a[i][1], a[i][2], a[i][3], bb0, bb1);
                }
            }
        }
    }

    int mrow = bm + wm + (lane >> 2);
    int ncol = bn + wn + 2 * (lane & 3);
    #pragma unroll
    for (int i = 0; i < 4; i++) {
        #pragma unroll
        for (int j = 0; j < 4; j++) {
            int n0 = ncol + j * 8;
            float b0 = bias[n0], b1 = bias[n0 + 1];
            int m0 = mrow + i * 16;
            size_t rb0 = (size_t)m0 * N + n0;
            size_t rb1 = (size_t)(m0 + 8) * N + n0;
            float2 v0 = { acc[i][j][0] + b0, acc[i][j][1] + b1 };
            float2 v1 = { acc[i][j][2] + b0, acc[i][j][3] + b1 };
            if (Ch) {
                *(uint32_t*)(Ch + rb0) = h2u(__floats2half2_rn(v0.x, v0.y));
                *(uint32_t*)(Ch + rb1) = h2u(__floats2half2_rn(v1.x, v1.y));
            } else {
                if (resid) {
                    float2 r0 = __half22float2(*(const __half2*)(resid + rb0));
                    float2 r1 = __half22float2(*(const __half2*)(resid + rb1));
                    v0.x += r0.x; v0.y += r0.y; v1.x += r1.x; v1.y += r1.y;
                }
                *(float2*)(Cf + rb0) = v0;
                *(float2*)(Cf + rb1) = v1;
            }
        }
    }
}

// ======================= HMMA flash attention: 256 threads, BQ=128, 2-stage (R11 config) =======================
#define TSTR2 136
#define TILE_E (64 * TSTR2)
#define STAGE_E (2 * TILE_E)
#define ATTN_SMEM (2 * STAGE_E * 2 + 512)

__global__ void __launch_bounds__(256, 1) k_attn_h(
    const int* __restrict__ seg,
    const __half* __restrict__ qkv,
    __half* __restrict__ attn_out)
{
    extern __shared__ char smc[];
    __half* buf = (__half*)smc;
    uint32_t buf_u = smem_u32(buf);
    uint32_t sks_u = buf_u + 2 * STAGE_E * 2;
    int* sks = (int*)(smc + 2 * STAGE_E * 2);

    const int t = threadIdx.x, lane = t & 31, w = t >> 5;
    const int q0 = blockIdx.x * 128, h = blockIdx.y;
    const int wq = w * 16;
    const float scale = 0.08838834764831845f;

    const int ldrow = (lane & 7) + ((lane & 8) ? 8 : 0);
    const int a_kof = (lane & 16) ? 8 : 0;
    const int b_row = (lane & 7) + ((lane & 16) ? 8 : 0);
    const int b_kof = (lane & 8) ? 8 : 0;
    const int v_col = (lane & 16) ? 8 : 0;

    #pragma unroll
    for (int i = 0; i < 8; i++) {
        int vid = t + i * 256;
        int row = vid >> 4, c = vid & 15;
        cpasync16(buf_u + (row * TSTR2 + c * 8) * 2,
                  qkv + (size_t)(q0 + row) * TD + h * HD + c * 8);
    }
    asm volatile("cp.async.commit_group;" ::: "memory");
    asm volatile("cp.async.wait_group 0;" ::: "memory");
    __syncthreads();

    uint32_t qa[8][4];
    #pragma unroll
    for (int ks = 0; ks < 8; ks++) {
        uint32_t addr = buf_u + (((wq + ldrow) * TSTR2) + ks * 16 + a_kof) * 2;
        ldsm4(qa[ks][0], qa[ks][1], qa[ks][2], qa[ks][3], addr);
    }
    int sq0 = seg[q0 + wq + (lane >> 2)];
    int sq1 = seg[q0 + wq + (lane >> 2) + 8];
    __syncthreads();

    float mv[2] = { -1e30f, -1e30f }, lv[2] = { 0.f, 0.f };
    float o[16][4];
    #pragma unroll
    for (int j = 0; j < 16; j++)
        #pragma unroll
        for (int c = 0; c < 4; c++) o[j][c] = 0.f;

    {
        #pragma unroll
        for (int i = 0; i < 4; i++) {
            int vid = t + i * 256;
            int row = vid >> 4, c = vid & 15;
            cpasync16(buf_u + (row * TSTR2 + c * 8) * 2,
                      qkv + (size_t)row * TD + DIM + h * HD + c * 8);
            cpasync16(buf_u + (TILE_E + row * TSTR2 + c * 8) * 2,
                      qkv + (size_t)row * TD + 2 * DIM + h * HD + c * 8);
        }
        if (t < 16) cpasync16(sks_u + t * 16, seg + t * 4);
        asm volatile("cp.async.commit_group;" ::: "memory");
    }

    const int NT = SEQ / 64;
    for (int kt = 0; kt < NT; kt++) {
        int st = kt & 1;
        if (kt + 1 < NT) {
            int ns = st ^ 1;
            int kb = (kt + 1) * 64;
            #pragma unroll
            for (int i = 0; i < 4; i++) {
                int vid = t + i * 256;
                int row = vid >> 4, c = vid & 15;
                cpasync16(buf_u + (ns * STAGE_E + row * TSTR2 + c * 8) * 2,
                          qkv + (size_t)(kb + row) * TD + DIM + h * HD + c * 8);
                cpasync16(buf_u + (ns * STAGE_E + TILE_E + row * TSTR2 + c * 8) * 2,
                          qkv + (size_t)(kb + row) * TD + 2 * DIM + h * HD + c * 8);
            }
            if (t < 16) cpasync16(sks_u + ns * 256 + t * 16, seg + kb + t * 4);
            asm volatile("cp.async.commit_group;" ::: "memory");
            asm volatile("cp.async.wait_group 1;" ::: "memory");
        } else {
            asm volatile("cp.async.wait_group 0;" ::: "memory");
        }
        __syncthreads();

        uint32_t kbase = buf_u + (st * STAGE_E) * 2;
        uint32_t vbase = kbase + TILE_E * 2;
        const int* skp = sks + st * 64;

        float s[8][4];
        #pragma unroll
        for (int j = 0; j < 8; j++)
            #pragma unroll
            for (int c = 0; c < 4; c++) s[j][c] = 0.f;

        #pragma unroll
        for (int ks = 0; ks < 8; ks++) {
            uint32_t kb_[4][4];
            #pragma unroll
            for (int g = 0; g < 4; g++) {
                uint32_t addr = kbase + (((g * 16 + b_row) * TSTR2) + ks * 16 + b_kof) * 2;
                ldsm4(kb_[g][0], kb_[g][1], kb_[g][2], kb_[g][3], addr);
            }
            #pragma unroll
            for (int g = 0; g < 4; g++) {
                mma16816(s[2*g],   qa[ks][0], qa[ks][1], qa[ks][2], qa[ks][3], kb_[g][0], kb_[g][1]);
                mma16816(s[2*g+1], qa[ks][0], qa[ks][1], qa[ks][2], qa[ks][3], kb_[g][2], kb_[g][3]);
            }
        }

        #pragma unroll
        for (int rh = 0; rh < 2; rh++) {
            int sqv = rh ? sq1 : sq0;
            float rm = -1e30f;
            #pragma unroll
            for (int j = 0; j < 8; j++) {
                #pragma unroll
                for (int cc = 0; cc < 2; cc++) {
                    int col = 8 * j + 2 * (lane & 3) + cc;
                    float v = s[j][2*rh+cc] * scale + ((sqv == skp[col]) ? 1.0f : 0.0f);
                    s[j][2*rh+cc] = v;
                    rm = fmaxf(rm, v);
                }
            }
            rm = fmaxf(rm, __shfl_xor_sync(0xffffffffu, rm, 1));
            rm = fmaxf(rm, __shfl_xor_sync(0xffffffffu, rm, 2));
            float mnew = fmaxf(mv[rh], rm);
            float corr = __expf(mv[rh] - mnew);
            mv[rh] = mnew;
            float rs = 0.f;
            #pragma unroll
            for (int j = 0; j < 8; j++) {
                #pragma unroll
                for (int cc = 0; cc < 2; cc++) {
                    float e = __expf(s[j][2*rh+cc] - mnew);
                    s[j][2*rh+cc] = e;
                    rs += e;
                }
            }
            rs += __shfl_xor_sync(0xffffffffu, rs, 1);
            rs += __shfl_xor_sync(0xffffffffu, rs, 2);
            lv[rh] = lv[rh] * corr + rs;
            #pragma unroll
            for (int j = 0; j < 16; j++) {
                o[j][2*rh]   *= corr;
                o[j][2*rh+1] *= corr;
            }
        }

        uint32_t pa[4][4];
        #pragma unroll
        for (int kk = 0; kk < 4; kk++) {
            pa[kk][0] = h2u(__floats2half2_rn(s[2*kk][0],   s[2*kk][1]));
            pa[kk][1] = h2u(__floats2half2_rn(s[2*kk][2],   s[2*kk][3]));
            pa[kk][2] = h2u(__floats2half2_rn(s[2*kk+1][0], s[2*kk+1][1]));
            pa[kk][3] = h2u(__floats2half2_rn(s[2*kk+1][2], s[2*kk+1][3]));
        }

        #pragma unroll
        for (int kk = 0; kk < 4; kk++) {
            #pragma unroll
            for (int g = 0; g < 8; g++) {
                uint32_t vb0, vb1, vb2, vb3;
                uint32_t addr = vbase + (((kk * 16 + ldrow) * TSTR2) + g * 16 + v_col) * 2;
                ldsm4t(vb0, vb1, vb2, vb3, addr);
                mma16816(o[2*g],   pa[kk][0], pa[kk][1], pa[kk][2], pa[kk][3], vb0, vb1);
                mma16816(o[2*g+1], pa[kk][0], pa[kk][1], pa[kk][2], pa[kk][3], vb2, vb3);
            }
        }
        __syncthreads();
    }

    float inv0 = 1.0f / lv[0], inv1 = 1.0f / lv[1];
    int r0 = q0 + wq + (lane >> 2);
    int colb = 2 * (lane & 3);
    #pragma unroll
    for (int j = 0; j < 16; j++) {
        int col = h * HD + 8 * j + colb;
        *(uint32_t*)(attn_out + (size_t)r0 * DIM + col) =
            h2u(__floats2half2_rn(o[j][0] * inv0, o[j][1] * inv0));
        *(uint32_t*)(attn_out + (size_t)(r0 + 8) * DIM + col) =
            h2u(__floats2half2_rn(o[j][2] * inv1, o[j][3] * inv1));
    }
}

// ======================= fused prep: w1 convert + embed+LN (w2 moved into QKV launch) =======================
#define NB_W1 (TD * DIM / 8 / 256)    // 6144

__global__ void __launch_bounds__(256) k_prep(
    const float* __restrict__ in_w,
    const float* __restrict__ byte_repr,
    const int*   __restrict__ cats,
    const int*   __restrict__ cse,
    const int*   __restrict__ comb,
    const float* __restrict__ cat_emb,
    const float* __restrict__ case_emb,
    const float* __restrict__ comb_emb,
    const float* __restrict__ g,
    const float* __restrict__ b)
{
    int blk = blockIdx.x;
    int t = threadIdx.x;

    if (blk < NB_W1) {
        int i = blk * 256 + t;
        float4 a = ld4(in_w + (size_t)i * 8);
        float4 c = ld4(in_w + (size_t)i * 8 + 4);
        __half2 h[4];
        h[0] = __floats2half2_rn(a.x, a.y);
        h[1] = __floats2half2_rn(a.z, a.w);
        h[2] = __floats2half2_rn(c.x, c.y);
        h[3] = __floats2half2_rn(c.z, c.w);
        *(uint4*)(g_w1_h + (size_t)i * 8) = *(uint4*)h;
        return;
    }

    int s = blk - NB_W1;
    int lane = t & 31, wid = t >> 5;
    int c0 = t * 4;
    int c1 = 1024 + t * 4;

    size_t catb = (size_t)cats[s] * DIM;
    size_t cab  = (size_t)cse[s]  * DIM;
    size_t cob  = (size_t)comb[s] * DIM;
    const float* base = byte_repr + (size_t)s * DIM;

    float x[8];
    {
        float4 a = ld4(base + c0), e = ld4(cat_emb + catb + c0);
        float4 f = ld4(case_emb + cab + c0), h = ld4(comb_emb + cob + c0);
        x[0] = a.x + e.x + f.x + h.x;  x[1] = a.y + e.y + f.y + h.y;
        x[2] = a.z + e.z + f.z + h.z;  x[3] = a.w + e.w + f.w + h.w;
    }
    {
        float4 a = ld4(base + c1), e = ld4(cat_emb + catb + c1);
        float4 f = ld4(case_emb + cab + c1), h = ld4(comb_emb + cob + c1);
        x[4] = a.x + e.x + f.x + h.x;  x[5] = a.y + e.y + f.y + h.y;
        x[6] = a.z + e.z + f.z + h.z;  x[7] = a.w + e.w + f.w + h.w;
    }

    __shared__ float red[8];
    __shared__ float s_bcast;

    float sum = 0.f;
    #pragma unroll
    for (int i = 0; i < 8; i++) sum += x[i];
    #pragma unroll
    for (int o = 16; o > 0; o >>= 1) sum += __shfl_xor_sync(0xffffffffu, sum, o);
    if (lane == 0) red[wid] = sum;
    __syncthreads();
    if (t == 0) {
        float v = 0.f;
        #pragma unroll
        for (int i = 0; i < 8; i++) v += red[i];
        s_bcast = v * (1.0f / DIM);
    }
    __syncthreads();
    float mu = s_bcast;
    __syncthreads();

    float sq = 0.f;
    #pragma unroll
    for (int i = 0; i < 8; i++) { float d = x[i] - mu; sq += d * d; }
    #pragma unroll
    for (int o = 16; o > 0; o >>= 1) sq += __shfl_xor_sync(0xffffffffu, sq, o);
    if (lane == 0) red[wid] = sq;
    __syncthreads();
    if (t == 0) {
        float v = 0.f;
        #pragma unroll
        for (int i = 0; i < 8; i++) v += red[i];
        s_bcast = rsqrtf(v * (1.0f / DIM) + LN_EPS);
    }
    __syncthreads();
    float rs = s_bcast;

    __half* dsth = g_xn_h + (size_t)s * DIM;
    {
        float4 gg = ld4(g + c0), bb = ld4(b + c0);
        float4 o;
        o.x = (x[0] - mu) * rs * gg.x + bb.x;
        o.y = (x[1] - mu) * rs * gg.y + bb.y;
        o.z = (x[2] - mu) * rs * gg.z + bb.z;
        o.w = (x[3] - mu) * rs * gg.w + bb.w;
        __half2 h2[2] = { __floats2half2_rn(o.x, o.y), __floats2half2_rn(o.z, o.w) };
        *(uint2*)(dsth + c0) = *(uint2*)h2;
    }
    {
        float4 gg = ld4(g + c1), bb = ld4(b + c1);
        float4 o;
        o.x = (x[4] - mu) * rs * gg.x + bb.x;
        o.y = (x[5] - mu) * rs * gg.y + bb.y;
        o.z = (x[6] - mu) * rs * gg.z + bb.z;
        o.w = (x[7] - mu) * rs * gg.w + bb.w;
        __half2 h2[2] = { __floats2half2_rn(o.x, o.y), __floats2half2_rn(o.z, o.w) };
        *(uint2*)(dsth + c1) = *(uint2*)h2;
    }
}

// ======================= launcher =======================
extern "C" void kernel_launch(void* const* d_in, const int* in_sizes, int n_in,
                              void* d_out, int out_size)
{
    const float* byte_repr = (const float*)d_in[0];
    const int*   categories= (const int*)  d_in[1];
    const int*   cse       = (const int*)  d_in[2];
    const int*   comb      = (const int*)  d_in[3];
    const int*   seg_ids   = (const int*)  d_in[4];
    const float* cat_emb   = (const float*)d_in[5];
    const float* case_emb  = (const float*)d_in[6];
    const float* comb_emb  = (const float*)d_in[7];
    const float* ln_g      = (const float*)d_in[8];
    const float* ln_b      = (const float*)d_in[9];
    const float* in_w      = (const float*)d_in[10];
    const float* in_b      = (const float*)d_in[11];
    const float* out_w     = (const float*)d_in[12];
    const float* out_b     = (const float*)d_in[13];
    float* out = (float*)d_out;

    __half *p_xn_h, *p_qkv_h, *p_attn_h, *p_w1_h, *p_w2_h;
    cudaGetSymbolAddress((void**)&p_xn_h,  g_xn_h);
    cudaGetSymbolAddress((void**)&p_qkv_h, g_qkv_h);
    cudaGetSymbolAddress((void**)&p_attn_h,g_attn_h);
    cudaGetSymbolAddress((void**)&p_w1_h,  g_w1_h);
    cudaGetSymbolAddress((void**)&p_w2_h,  g_w2_h);

    cudaFuncSetAttribute(k_attn_h, cudaFuncAttributeMaxDynamicSharedMemorySize, ATTN_SMEM);
    cudaFuncSetAttribute(h_gemm, cudaFuncAttributeMaxDynamicSharedMemorySize, GEMM_SMEM);

    // 1) fused prep: w1 convert + embed+LN (w2 convert rides inside QKV GEMM)
    k_prep<<<NB_W1 + SEQ, 256>>>(in_w, byte_repr, categories, cse, comb,
                                 cat_emb, case_emb, comb_emb, ln_g, ln_b);

    // 2) QKV projection -> f16, with piggybacked w2 fp32->f16 convert (extra grid row)
    dim3 gq(TD / 128, SEQ / 128 + 1);
    h_gemm<<<gq, 256, GEMM_SMEM>>>(p_xn_h, p_w1_h, in_b, nullptr, nullptr, p_qkv_h,
                                   SEQ, TD, DIM, out_w, p_w2_h, DIM * DIM / 8);

    // 3) HMMA flash attention (256 threads, BQ=128, 2-stage)
    dim3 ga(SEQ / 128, NH);
    k_attn_h<<<ga, 256, ATTN_SMEM>>>(seg_ids, p_qkv_h, p_attn_h);

    // 4) out projection + f16 residual -> fp32 out
    dim3 go(DIM / 128, SEQ / 128);
    h_gemm<<<go, 256, GEMM_SMEM>>>(p_attn_h, p_w2_h, out_b, p_xn_h, out, nullptr,
                                   SEQ, DIM, DIM, nullptr, nullptr, 0);
}

// round 15
// speedup vs baseline: 1.0231x; 1.0054x over previous
#include <cuda_runtime.h>
#include <cuda_fp16.h>
#include <cstdint>

#define SEQ 2048
#define DIM 2048
#define NH  16
#define HD  128
#define TD  (3*DIM)
#define LN_EPS 1e-5f

// ---------------- scratch (static device globals; no allocation) ----------------
__device__ __half g_xn_h[(size_t)SEQ*DIM];    // f16 LN output (GEMM A operand + residual)
__device__ __half g_qkv_h[(size_t)SEQ*TD];    // f16 QKV
__device__ __half g_attn_h[(size_t)SEQ*DIM];  // f16 attention output
__device__ __half g_w1_h[(size_t)TD*DIM];
__device__ __half g_w2_h[(size_t)DIM*DIM];

__device__ __forceinline__ float4 ld4(const float* p){ return *(const float4*)p; }

// ---------------- MMA helpers ----------------
__device__ __forceinline__ uint32_t smem_u32(const void* p){
    uint32_t a; asm("{ .reg .u64 t; cvta.to.shared.u64 t, %1; cvt.u32.u64 %0, t; }" : "=r"(a) : "l"(p)); return a;
}
__device__ __forceinline__ void ldsm4(uint32_t& r0, uint32_t& r1, uint32_t& r2, uint32_t& r3, uint32_t a){
    asm volatile("ldmatrix.sync.aligned.m8n8.x4.shared.b16 {%0,%1,%2,%3}, [%4];"
                 : "=r"(r0), "=r"(r1), "=r"(r2), "=r"(r3) : "r"(a));
}
__device__ __forceinline__ void ldsm4t(uint32_t& r0, uint32_t& r1, uint32_t& r2, uint32_t& r3, uint32_t a){
    asm volatile("ldmatrix.sync.aligned.m8n8.x4.trans.shared.b16 {%0,%1,%2,%3}, [%4];"
                 : "=r"(r0), "=r"(r1), "=r"(r2), "=r"(r3) : "r"(a));
}
__device__ __forceinline__ void mma16816(float* c, uint32_t a0, uint32_t a1, uint32_t a2, uint32_t a3,
                                         uint32_t b0, uint32_t b1){
    asm volatile("mma.sync.aligned.m16n8k16.row.col.f32.f16.f16.f32 "
                 "{%0,%1,%2,%3}, {%4,%5,%6,%7}, {%8,%9}, {%0,%1,%2,%3};"
                 : "+f"(c[0]), "+f"(c[1]), "+f"(c[2]), "+f"(c[3])
                 : "r"(a0), "r"(a1), "r"(a2), "r"(a3), "r"(b0), "r"(b1));
}
__device__ __forceinline__ void cpasync16(uint32_t dst, const void* src){
    asm volatile("cp.async.cg.shared.global [%0], [%1], 16;" :: "r"(dst), "l"(src));
}
__device__ __forceinline__ uint32_t h2u(__half2 h){ return *(uint32_t*)&h; }

// ================= HMMA f16 GEMM-NT: 128x128 tile, BK=64, 3-stage swizzled, 1 sync/iter =================
// Optional piggyback convert: blocks with blockIdx.y == gridDim.y-1 (when csrc != null)
// perform a grid-stride fp32->f16 convert instead of GEMM work.
#define BK 64
#define STG_A (128 * 128)                // 16384 B per tile
#define STG_BYTES (2 * STG_A)            // 32768
#define GEMM_SMEM (3 * STG_BYTES)        // 98304 -> 2 CTA/SM

__global__ void __launch_bounds__(256) h_gemm(
    const __half* __restrict__ A, const __half* __restrict__ B,
    const float* __restrict__ bias, const __half* __restrict__ resid,
    float* __restrict__ Cf, __half* __restrict__ Ch, int M, int N, int K,
    const float* __restrict__ csrc, __half* __restrict__ cdst, int cn8)
{
    extern __shared__ char smc[];
    uint32_t base = smem_u32(smc);

    int t = threadIdx.x, lane = t & 31, w = t >> 5;

    // ---- piggyback convert row ----
    if (csrc && (int)blockIdx.y == (int)gridDim.y - 1) {
        int stride = gridDim.x * 256;
        for (int i = blockIdx.x * 256 + t; i < cn8; i += stride) {
            float4 a = ld4(csrc + (size_t)i * 8);
            float4 c = ld4(csrc + (size_t)i * 8 + 4);
            __half2 h[4];
            h[0] = __floats2half2_rn(a.x, a.y);
            h[1] = __floats2half2_rn(a.z, a.w);
            h[2] = __floats2half2_rn(c.x, c.y);
            h[3] = __floats2half2_rn(c.z, c.w);
            *(uint4*)(cdst + (size_t)i * 8) = *(uint4*)h;
        }
        return;
    }

    int bm = blockIdx.y * 128, bn = blockIdx.x * 128;
    int wm = (w >> 2) * 64, wn = (w & 3) * 32;

    int a_row = wm + (lane & 7) + ((lane & 8) ? 8 : 0);
    int a_kc  = (lane & 16) ? 1 : 0;
    int b_row = wn + (lane & 7) + ((lane & 16) ? 8 : 0);
    int b_kc  = (lane & 8) ? 1 : 0;

    float acc[4][4][4];
    #pragma unroll
    for (int i = 0; i < 4; i++)
        #pragma unroll
        for (int j = 0; j < 4; j++)
            #pragma unroll
            for (int c = 0; c < 4; c++) acc[i][j][c] = 0.f;

    int niter = K / BK;

    auto load_stage = [&](int stg, int kc){
        uint32_t ab = base + stg * STG_BYTES;
        uint32_t bb = ab + STG_A;
        const __half* Ak = A + (size_t)kc * BK;
        const __half* Bk = B + (size_t)kc * BK;
        #pragma unroll
        for (int i = 0; i < 4; i++) {
            int vid = t + i * 256;
            int row = vid >> 3, c = vid & 7;
            int sw = ((c ^ (row & 7)) << 4);
            cpasync16(ab + row * 128 + sw, Ak + (size_t)(bm + row) * K + c * 8);
        }
        #pragma unroll
        for (int i = 0; i < 4; i++) {
            int vid = t + i * 256;
            int row = vid >> 3, c = vid & 7;
            int sw = ((c ^ (row & 7)) << 4);
            cpasync16(bb + row * 128 + sw, Bk + (size_t)(bn + row) * K + c * 8);
        }
        asm volatile("cp.async.commit_group;" ::: "memory");
    };

    load_stage(0, 0);
    if (niter > 1) load_stage(1, 1);

    for (int kt = 0; kt < niter; kt++) {
        if (kt + 1 < niter) {
            asm volatile("cp.async.wait_group 1;" ::: "memory");
        } else {
            asm volatile("cp.async.wait_group 0;" ::: "memory");
        }
        __syncthreads();
        if (kt + 2 < niter) load_stage((kt + 2) % 3, kt + 2);

        int stg = kt % 3;
        uint32_t abase = base + stg * STG_BYTES;
        uint32_t bbase = abase + STG_A;
        #pragma unroll
        for (int ks = 0; ks < 4; ks++) {
            // B fragments first (consumed first), then A; pair mmas with ready data
            uint32_t b[2][4], a[4][4];
            #pragma unroll
            for (int p = 0; p < 2; p++) {
                int br = b_row + p * 16;
                int ch = ks * 2 + b_kc;
                uint32_t addr = bbase + br * 128 + (((ch ^ (br & 7)) << 4));
                ldsm4(b[p][0], b[p][1], b[p][2], b[p][3], addr);
            }
            #pragma unroll
            for (int i = 0; i < 4; i++) {
                int ar = a_row + i * 16;
                int ch = ks * 2 + a_kc;
                uint32_t addr = abase + ar * 128 + (((ch ^ (ar & 7)) << 4));
                ldsm4(a[i][0], a[i][1], a[i][2], a[i][3], addr);
            }
            #pragma unroll
            for (int i = 0; i < 4; i++) {
                mma16816(acc[i][0], a[i][0], a[i][1], a[i][2], a[i][3], b[0][0], b[0][1]);
                mma16816(acc[i][1], a[i][0], a[i][1], a[i][2], a[i][3], b[0][2], b[0][3]);
                mma16816(acc[i][2], a[i][0], a[i][1], a[i][2], a[i][3], b[1][0], b[1][1]);
                mma16816(acc[i][3], a[i][0], a[i][1], a[i][2], a[i][3], b[1][2], b[1][3]);
            }
        }
    }

    int mrow = bm + wm + (lane >> 2);
    int ncol = bn + wn + 2 * (lane & 3);
    #pragma unroll
    for (int i = 0; i < 4; i++) {
        #pragma unroll
        for (int j = 0; j < 4; j++) {
            int n0 = ncol + j * 8;
            float b0 = bias[n0], b1 = bias[n0 + 1];
            int m0 = mrow + i * 16;
            size_t rb0 = (size_t)m0 * N + n0;
            size_t rb1 = (size_t)(m0 + 8) * N + n0;
            float2 v0 = { acc[i][j][0] + b0, acc[i][j][1] + b1 };
            float2 v1 = { acc[i][j][2] + b0, acc[i][j][3] + b1 };
            if (Ch) {
                *(uint32_t*)(Ch + rb0) = h2u(__floats2half2_rn(v0.x, v0.y));
                *(uint32_t*)(Ch + rb1) = h2u(__floats2half2_rn(v1.x, v1.y));
            } else {
                if (resid) {
                    float2 r0 = __half22float2(*(const __half2*)(resid + rb0));
                    float2 r1 = __half22float2(*(const __half2*)(resid + rb1));
                    v0.x += r0.x; v0.y += r0.y; v1.x += r1.x; v1.y += r1.y;
                }
                *(float2*)(Cf + rb0) = v0;
                *(float2*)(Cf + rb1) = v1;
            }
        }
    }
}

// ======================= HMMA flash attention: 256 threads, BQ=128, 2-stage (R11 config) =======================
#define TSTR2 136
#define TILE_E (64 * TSTR2)
#define STAGE_E (2 * TILE_E)
#define ATTN_SMEM (2 * STAGE_E * 2 + 512)

__global__ void __launch_bounds__(256, 1) k_attn_h(
    const int* __restrict__ seg,
    const __half* __restrict__ qkv,
    __half* __restrict__ attn_out)
{
    extern __shared__ char smc[];
    __half* buf = (__half*)smc;
    uint32_t buf_u = smem_u32(buf);
    uint32_t sks_u = buf_u + 2 * STAGE_E * 2;
    int* sks = (int*)(smc + 2 * STAGE_E * 2);

    const int t = threadIdx.x, lane = t & 31, w = t >> 5;
    const int q0 = blockIdx.x * 128, h = blockIdx.y;
    const int wq = w * 16;
    const float scale = 0.08838834764831845f;

    const int ldrow = (lane & 7) + ((lane & 8) ? 8 : 0);
    const int a_kof = (lane & 16) ? 8 : 0;
    const int b_row = (lane & 7) + ((lane & 16) ? 8 : 0);
    const int b_kof = (lane & 8) ? 8 : 0;
    const int v_col = (lane & 16) ? 8 : 0;

    #pragma unroll
    for (int i = 0; i < 8; i++) {
        int vid = t + i * 256;
        int row = vid >> 4, c = vid & 15;
        cpasync16(buf_u + (row * TSTR2 + c * 8) * 2,
                  qkv + (size_t)(q0 + row) * TD + h * HD + c * 8);
    }
    asm volatile("cp.async.commit_group;" ::: "memory");
    asm volatile("cp.async.wait_group 0;" ::: "memory");
    __syncthreads();

    uint32_t qa[8][4];
    #pragma unroll
    for (int ks = 0; ks < 8; ks++) {
        uint32_t addr = buf_u + (((wq + ldrow) * TSTR2) + ks * 16 + a_kof) * 2;
        ldsm4(qa[ks][0], qa[ks][1], qa[ks][2], qa[ks][3], addr);
    }
    int sq0 = seg[q0 + wq + (lane >> 2)];
    int sq1 = seg[q0 + wq + (lane >> 2) + 8];
    __syncthreads();

    float mv[2] = { -1e30f, -1e30f }, lv[2] = { 0.f, 0.f };
    float o[16][4];
    #pragma unroll
    for (int j = 0; j < 16; j++)
        #pragma unroll
        for (int c = 0; c < 4; c++) o[j][c] = 0.f;

    {
        #pragma unroll
        for (int i = 0; i < 4; i++) {
            int vid = t + i * 256;
            int row = vid >> 4, c = vid & 15;
            cpasync16(buf_u + (row * TSTR2 + c * 8) * 2,
                      qkv + (size_t)row * TD + DIM + h * HD + c * 8);
            cpasync16(buf_u + (TILE_E + row * TSTR2 + c * 8) * 2,
                      qkv + (size_t)row * TD + 2 * DIM + h * HD + c * 8);
        }
        if (t < 16) cpasync16(sks_u + t * 16, seg + t * 4);
        asm volatile("cp.async.commit_group;" ::: "memory");
    }

    const int NT = SEQ / 64;
    for (int kt = 0; kt < NT; kt++) {
        int st = kt & 1;
        if (kt + 1 < NT) {
            int ns = st ^ 1;
            int kb = (kt + 1) * 64;
            #pragma unroll
            for (int i = 0; i < 4; i++) {
                int vid = t + i * 256;
                int row = vid >> 4, c = vid & 15;
                cpasync16(buf_u + (ns * STAGE_E + row * TSTR2 + c * 8) * 2,
                          qkv + (size_t)(kb + row) * TD + DIM + h * HD + c * 8);
                cpasync16(buf_u + (ns * STAGE_E + TILE_E + row * TSTR2 + c * 8) * 2,
                          qkv + (size_t)(kb + row) * TD + 2 * DIM + h * HD + c * 8);
            }
            if (t < 16) cpasync16(sks_u + ns * 256 + t * 16, seg + kb + t * 4);
            asm volatile("cp.async.commit_group;" ::: "memory");
            asm volatile("cp.async.wait_group 1;" ::: "memory");
        } else {
            asm volatile("cp.async.wait_group 0;" ::: "memory");
        }
        __syncthreads();

        uint32_t kbase = buf_u + (st * STAGE_E) * 2;
        uint32_t vbase = kbase + TILE_E * 2;
        const int* skp = sks + st * 64;

        float s[8][4];
        #pragma unroll
        for (int j = 0; j < 8; j++)
            #pragma unroll
            for (int c = 0; c < 4; c++) s[j][c] = 0.f;

        #pragma unroll
        for (int ks = 0; ks < 8; ks++) {
            uint32_t kb_[4][4];
            #pragma unroll
            for (int g = 0; g < 4; g++) {
                uint32_t addr = kbase + (((g * 16 + b_row) * TSTR2) + ks * 16 + b_kof) * 2;
                ldsm4(kb_[g][0], kb_[g][1], kb_[g][2], kb_[g][3], addr);
            }
            #pragma unroll
            for (int g = 0; g < 4; g++) {
                mma16816(s[2*g],   qa[ks][0], qa[ks][1], qa[ks][2], qa[ks][3], kb_[g][0], kb_[g][1]);
                mma16816(s[2*g+1], qa[ks][0], qa[ks][1], qa[ks][2], qa[ks][3], kb_[g][2], kb_[g][3]);
            }
        }

        #pragma unroll
        for (int rh = 0; rh < 2; rh++) {
            int sqv = rh ? sq1 : sq0;
            float rm = -1e30f;
            #pragma unroll
            for (int j = 0; j < 8; j++) {
                #pragma unroll
                for (int cc = 0; cc < 2; cc++) {
                    int col = 8 * j + 2 * (lane & 3) + cc;
                    float v = s[j][2*rh+cc] * scale + ((sqv == skp[col]) ? 1.0f : 0.0f);
                    s[j][2*rh+cc] = v;
                    rm = fmaxf(rm, v);
                }
            }
            rm = fmaxf(rm, __shfl_xor_sync(0xffffffffu, rm, 1));
            rm = fmaxf(rm, __shfl_xor_sync(0xffffffffu, rm, 2));
            float mnew = fmaxf(mv[rh], rm);
            float corr = __expf(mv[rh] - mnew);
            mv[rh] = mnew;
            float rs = 0.f;
            #pragma unroll
            for (int j = 0; j < 8; j++) {
                #pragma unroll
                for (int cc = 0; cc < 2; cc++) {
                    float e = __expf(s[j][2*rh+cc] - mnew);
                    s[j][2*rh+cc] = e;
                    rs += e;
                }
            }
            rs += __shfl_xor_sync(0xffffffffu, rs, 1);
            rs += __shfl_xor_sync(0xffffffffu, rs, 2);
            lv[rh] = lv[rh] * corr + rs;
            #pragma unroll
            for (int j = 0; j < 16; j++) {
                o[j][2*rh]   *= corr;
                o[j][2*rh+1] *= corr;
            }
        }

        uint32_t pa[4][4];
        #pragma unroll
        for (int kk = 0; kk < 4; kk++) {
            pa[kk][0] = h2u(__floats2half2_rn(s[2*kk][0],   s[2*kk][1]));
            pa[kk][1] = h2u(__floats2half2_rn(s[2*kk][2],   s[2*kk][3]));
            pa[kk][2] = h2u(__floats2half2_rn(s[2*kk+1][0], s[2*kk+1][1]));
            pa[kk][3] = h2u(__floats2half2_rn(s[2*kk+1][2], s[2*kk+1][3]));
        }

        #pragma unroll
        for (int kk = 0; kk < 4; kk++) {
            #pragma unroll
            for (int g = 0; g < 8; g++) {
                uint32_t vb0, vb1, vb2, vb3;
                uint32_t addr = vbase + (((kk * 16 + ldrow) * TSTR2) + g * 16 + v_col) * 2;
                ldsm4t(vb0, vb1, vb2, vb3, addr);
                mma16816(o[2*g],   pa[kk][0], pa[kk][1], pa[kk][2], pa[kk][3], vb0, vb1);
                mma16816(o[2*g+1], pa[kk][0], pa[kk][1], pa[kk][2], pa[kk][3], vb2, vb3);
            }
        }
        __syncthreads();
    }

    float inv0 = 1.0f / lv[0], inv1 = 1.0f / lv[1];
    int r0 = q0 + wq + (lane >> 2);
    int colb = 2 * (lane & 3);
    #pragma unroll
    for (int j = 0; j < 16; j++) {
        int col = h * HD + 8 * j + colb;
        *(uint32_t*)(attn_out + (size_t)r0 * DIM + col) =
            h2u(__floats2half2_rn(o[j][0] * inv0, o[j][1] * inv0));
        *(uint32_t*)(attn_out + (size_t)(r0 + 8) * DIM + col) =
            h2u(__floats2half2_rn(o[j][2] * inv1, o[j][3] * inv1));
    }
}

// ======================= fused prep: w1 convert + embed+LN (w2 moved into QKV launch) =======================
#define NB_W1 (TD * DIM / 8 / 256)    // 6144

__global__ void __launch_bounds__(256) k_prep(
    const float* __restrict__ in_w,
    const float* __restrict__ byte_repr,
    const int*   __restrict__ cats,
    const int*   __restrict__ cse,
    const int*   __restrict__ comb,
    const float* __restrict__ cat_emb,
    const float* __restrict__ case_emb,
    const float* __restrict__ comb_emb,
    const float* __restrict__ g,
    const float* __restrict__ b)
{
    int blk = blockIdx.x;
    int t = threadIdx.x;

    if (blk < NB_W1) {
        int i = blk * 256 + t;
        float4 a = ld4(in_w + (size_t)i * 8);
        float4 c = ld4(in_w + (size_t)i * 8 + 4);
        __half2 h[4];
        h[0] = __floats2half2_rn(a.x, a.y);
        h[1] = __floats2half2_rn(a.z, a.w);
        h[2] = __floats2half2_rn(c.x, c.y);
        h[3] = __floats2half2_rn(c.z, c.w);
        *(uint4*)(g_w1_h + (size_t)i * 8) = *(uint4*)h;
        return;
    }

    int s = blk - NB_W1;
    int lane = t & 31, wid = t >> 5;
    int c0 = t * 4;
    int c1 = 1024 + t * 4;

    size_t catb = (size_t)cats[s] * DIM;
    size_t cab  = (size_t)cse[s]  * DIM;
    size_t cob  = (size_t)comb[s] * DIM;
    const float* base = byte_repr + (size_t)s * DIM;

    float x[8];
    {
        float4 a = ld4(base + c0), e = ld4(cat_emb + catb + c0);
        float4 f = ld4(case_emb + cab + c0), h = ld4(comb_emb + cob + c0);
        x[0] = a.x + e.x + f.x + h.x;  x[1] = a.y + e.y + f.y + h.y;
        x[2] = a.z + e.z + f.z + h.z;  x[3] = a.w + e.w + f.w + h.w;
    }
    {
        float4 a = ld4(base + c1), e = ld4(cat_emb + catb + c1);
        float4 f = ld4(case_emb + cab + c1), h = ld4(comb_emb + cob + c1);
        x[4] = a.x + e.x + f.x + h.x;  x[5] = a.y + e.y + f.y + h.y;
        x[6] = a.z + e.z + f.z + h.z;  x[7] = a.w + e.w + f.w + h.w;
    }

    __shared__ float red[8];
    __shared__ float s_bcast;

    float sum = 0.f;
    #pragma unroll
    for (int i = 0; i < 8; i++) sum += x[i];
    #pragma unroll
    for (int o = 16; o > 0; o >>= 1) sum += __shfl_xor_sync(0xffffffffu, sum, o);
    if (lane == 0) red[wid] = sum;
    __syncthreads();
    if (t == 0) {
        float v = 0.f;
        #pragma unroll
        for (int i = 0; i < 8; i++) v += red[i];
        s_bcast = v * (1.0f / DIM);
    }
    __syncthreads();
    float mu = s_bcast;
    __syncthreads();

    float sq = 0.f;
    #pragma unroll
    for (int i = 0; i < 8; i++) { float d = x[i] - mu; sq += d * d; }
    #pragma unroll
    for (int o = 16; o > 0; o >>= 1) sq += __shfl_xor_sync(0xffffffffu, sq, o);
    if (lane == 0) red[wid] = sq;
    __syncthreads();
    if (t == 0) {
        float v = 0.f;
        #pragma unroll
        for (int i = 0; i < 8; i++) v += red[i];
        s_bcast = rsqrtf(v * (1.0f / DIM) + LN_EPS);
    }
    __syncthreads();
    float rs = s_bcast;

    __half* dsth = g_xn_h + (size_t)s * DIM;
    {
        float4 gg = ld4(g + c0), bb = ld4(b + c0);
        float4 o;
        o.x = (x[0] - mu) * rs * gg.x + bb.x;
        o.y = (x[1] - mu) * rs * gg.y + bb.y;
        o.z = (x[2] - mu) * rs * gg.z + bb.z;
        o.w = (x[3] - mu) * rs * gg.w + bb.w;
        __half2 h2[2] = { __floats2half2_rn(o.x, o.y), __floats2half2_rn(o.z, o.w) };
        *(uint2*)(dsth + c0) = *(uint2*)h2;
    }
    {
        float4 gg = ld4(g + c1), bb = ld4(b + c1);
        float4 o;
        o.x = (x[4] - mu) * rs * gg.x + bb.x;
        o.y = (x[5] - mu) * rs * gg.y + bb.y;
        o.z = (x[6] - mu) * rs * gg.z + bb.z;
        o.w = (x[7] - mu) * rs * gg.w + bb.w;
        __half2 h2[2] = { __floats2half2_rn(o.x, o.y), __floats2half2_rn(o.z, o.w) };
        *(uint2*)(dsth + c1) = *(uint2*)h2;
    }
}

// ======================= launcher =======================
extern "C" void kernel_launch(void* const* d_in, const int* in_sizes, int n_in,
                              void* d_out, int out_size)
{
    const float* byte_repr = (const float*)d_in[0];
    const int*   categories= (const int*)  d_in[1];
    const int*   cse       = (const int*)  d_in[2];
    const int*   comb      = (const int*)  d_in[3];
    const int*   seg_ids   = (const int*)  d_in[4];
    const float* cat_emb   = (const float*)d_in[5];
    const float* case_emb  = (const float*)d_in[6];
    const float* comb_emb  = (const float*)d_in[7];
    const float* ln_g      = (const float*)d_in[8];
    const float* ln_b      = (const float*)d_in[9];
    const float* in_w      = (const float*)d_in[10];
    const float* in_b      = (const float*)d_in[11];
    const float* out_w     = (const float*)d_in[12];
    const float* out_b     = (const float*)d_in[13];
    float* out = (float*)d_out;

    __half *p_xn_h, *p_qkv_h, *p_attn_h, *p_w1_h, *p_w2_h;
    cudaGetSymbolAddress((void**)&p_xn_h,  g_xn_h);
    cudaGetSymbolAddress((void**)&p_qkv_h, g_qkv_h);
    cudaGetSymbolAddress((void**)&p_attn_h,g_attn_h);
    cudaGetSymbolAddress((void**)&p_w1_h,  g_w1_h);
    cudaGetSymbolAddress((void**)&p_w2_h,  g_w2_h);

    cudaFuncSetAttribute(k_attn_h, cudaFuncAttributeMaxDynamicSharedMemorySize, ATTN_SMEM);
    cudaFuncSetAttribute(h_gemm, cudaFuncAttributeMaxDynamicSharedMemorySize, GEMM_SMEM);

    // 1) fused prep: w1 convert + embed+LN (w2 convert rides inside QKV GEMM)
    k_prep<<<NB_W1 + SEQ, 256>>>(in_w, byte_repr, categories, cse, comb,
                                 cat_emb, case_emb, comb_emb, ln_g, ln_b);

    // 2) QKV projection -> f16, with piggybacked w2 fp32->f16 convert (extra grid row)
    dim3 gq(TD / 128, SEQ / 128 + 1);
    h_gemm<<<gq, 256, GEMM_SMEM>>>(p_xn_h, p_w1_h, in_b, nullptr, nullptr, p_qkv_h,
                                   SEQ, TD, DIM, out_w, p_w2_h, DIM * DIM / 8);

    // 3) HMMA flash attention (256 threads, BQ=128, 2-stage)
    dim3 ga(SEQ / 128, NH);
    k_attn_h<<<ga, 256, ATTN_SMEM>>>(seg_ids, p_qkv_h, p_attn_h);

    // 4) out projection + f16 residual -> fp32 out
    dim3 go(DIM / 128, SEQ / 128);
    h_gemm<<<go, 256, GEMM_SMEM>>>(p_attn_h, p_w2_h, out_b, p_xn_h, out, nullptr,
                                   SEQ, DIM, DIM, nullptr, nullptr, 0);
}